// round 12
// baseline (speedup 1.0000x reference)
#include <cuda_runtime.h>
#include <cuda_bf16.h>
#include <cuda_fp16.h>
#include <cstdint>

// ---------------- problem constants ----------------
#define BS      4
#define LQ      4096
#define EMBED   256
#define NH      8
#define HD      32
#define LEVELS  4
#define NPTS    4
#define SUMP    16   // LEVELS*NPTS
#define LV      8500 // 80*80 + 40*40 + 20*20 + 10*10
#define VPAD    64   // halves of padding on each side of g_vh

// ---------------- scratch (static device globals; no allocation) ----------------
// v in fp16, layout [b][h][cell][HD], padded both ends for clamped-pair reads.
__device__ __half g_vh [(size_t)BS * NH * LV * HD + 2 * VPAD];
__device__ float g_off [(size_t)BS * LQ * EMBED];     // query @ W_off + b_off
__device__ float g_attn[(size_t)BS * LQ * NH * SUMP]; // query @ W_attn + b_attn
__device__ float g_mid [(size_t)BS * LQ * EMBED];     // sampled output before W_o

// ---------------- tf32 tensor-core GEMM: C = A[M,K] @ B[K,N] + bias[N] ----------
// 128x128 block tile, BK=16, 256 threads = 8 warps in 2x4 grid, warp tile 64x32.
// NMMA=3: error-compensated tf32 (Ootomo)  D += Ahi*Bhi + Ahi*Blo + Alo*Bhi.
// NMMA=1: plain tf32 (used where downstream sensitivity is low).
// 2-stage cp.async double buffering. HALF_OUT stores fp16 transposed v layout.
#define BM 128
#define BN 128
#define BK 16
#define A_STRIDE 20    // BK+4
#define B_STRIDE 136   // BN+8

__device__ __forceinline__ void mma_tf32(float* d, const uint32_t* a, const uint32_t* b)
{
    asm volatile(
        "mma.sync.aligned.m16n8k8.row.col.f32.tf32.tf32.f32 "
        "{%0,%1,%2,%3}, {%4,%5,%6,%7}, {%8,%9}, {%0,%1,%2,%3};\n"
        : "+f"(d[0]), "+f"(d[1]), "+f"(d[2]), "+f"(d[3])
        : "r"(a[0]), "r"(a[1]), "r"(a[2]), "r"(a[3]),
          "r"(b[0]), "r"(b[1]));
}

__device__ __forceinline__ uint32_t f2tf32(float x)
{
    uint32_t r;
    asm("cvt.rna.tf32.f32 %0, %1;" : "=r"(r) : "f"(x));
    return r;
}

__device__ __forceinline__ void cp_async16(void* smem_dst, const void* gsrc, int src_bytes)
{
    uint32_t s = (uint32_t)__cvta_generic_to_shared(smem_dst);
    asm volatile("cp.async.cg.shared.global [%0], [%1], 16, %2;\n"
                 :: "r"(s), "l"(gsrc), "r"(src_bytes));
}

template<bool HALF_OUT, int NMMA>
__global__ __launch_bounds__(256)
void gemm_tf32_bias(const float* __restrict__ A, const float* __restrict__ B,
                    const float* __restrict__ bias, float* __restrict__ C,
                    __half* __restrict__ Ch,
                    int M, int N, int K)
{
    __shared__ float As[2][BM][A_STRIDE];
    __shared__ float Bs[2][BK][B_STRIDE];

    const int tid  = threadIdx.x;
    const int lane = tid & 31;
    const int wrp  = tid >> 5;          // 0..7
    const int wy   = wrp >> 2;          // 0..1 : row group of 64
    const int wx   = wrp & 3;           // 0..3 : col group of 32
    const int bm   = blockIdx.y * BM;
    const int bn   = blockIdx.x * BN;

    const int lq = lane >> 2;           // 0..7
    const int lr = lane & 3;            // 0..3

    const int ar0 = tid >> 2;                 // 0..63
    const int ar1 = (tid + 256) >> 2;         // 64..127
    const int ac  = (tid & 3) << 2;           // 0,4,8,12
    const int br0 = tid >> 5;                 // 0..7
    const int br1 = (tid + 256) >> 5;         // 8..15
    const int bc  = (tid & 31) << 2;          // 0..124

    float acc[4][4][4] = {};            // [mt][nt][c0..c3]

    auto load_tiles = [&](int k0, int st) {
        {
            int row = ar0;
            int gr  = min(bm + row, M - 1);
            cp_async16(&As[st][row][ac], A + (size_t)gr * K + k0 + ac,
                       (bm + row < M) ? 16 : 0);
            row = ar1;
            gr  = min(bm + row, M - 1);
            cp_async16(&As[st][row][ac], A + (size_t)gr * K + k0 + ac,
                       (bm + row < M) ? 16 : 0);
        }
        cp_async16(&Bs[st][br0][bc], B + (size_t)(k0 + br0) * N + bn + bc, 16);
        cp_async16(&Bs[st][br1][bc], B + (size_t)(k0 + br1) * N + bn + bc, 16);
        asm volatile("cp.async.commit_group;\n");
    };

    load_tiles(0, 0);
    asm volatile("cp.async.wait_group 0;\n");
    __syncthreads();

    int st = 0;
    for (int k0 = 0; k0 < K; k0 += BK) {
        if (k0 + BK < K) load_tiles(k0 + BK, st ^ 1);

        #pragma unroll
        for (int k8 = 0; k8 < BK; k8 += 8) {
            uint32_t ahi[4][4], alo[4][4];
            #pragma unroll
            for (int mt = 0; mt < 4; mt++) {
                int r = wy * 64 + mt * 16 + lq;
                float a0 = As[st][r    ][k8 + lr    ];
                float a1 = As[st][r + 8][k8 + lr    ];
                float a2 = As[st][r    ][k8 + lr + 4];
                float a3 = As[st][r + 8][k8 + lr + 4];
                ahi[mt][0] = f2tf32(a0);
                ahi[mt][1] = f2tf32(a1);
                ahi[mt][2] = f2tf32(a2);
                ahi[mt][3] = f2tf32(a3);
                if (NMMA == 3) {
                    alo[mt][0] = __float_as_uint(a0 - __uint_as_float(ahi[mt][0]));
                    alo[mt][1] = __float_as_uint(a1 - __uint_as_float(ahi[mt][1]));
                    alo[mt][2] = __float_as_uint(a2 - __uint_as_float(ahi[mt][2]));
                    alo[mt][3] = __float_as_uint(a3 - __uint_as_float(ahi[mt][3]));
                }
            }
            uint32_t bhi[4][2], blo[4][2];
            #pragma unroll
            for (int nt = 0; nt < 4; nt++) {
                int c = wx * 32 + nt * 8 + lq;
                float b0 = Bs[st][k8 + lr    ][c];
                float b1 = Bs[st][k8 + lr + 4][c];
                bhi[nt][0] = f2tf32(b0);
                bhi[nt][1] = f2tf32(b1);
                if (NMMA == 3) {
                    blo[nt][0] = __float_as_uint(b0 - __uint_as_float(bhi[nt][0]));
                    blo[nt][1] = __float_as_uint(b1 - __uint_as_float(bhi[nt][1]));
                }
            }
            #pragma unroll
            for (int mt = 0; mt < 4; mt++)
                #pragma unroll
                for (int nt = 0; nt < 4; nt++) {
                    mma_tf32(acc[mt][nt], ahi[mt], bhi[nt]);      // hi*hi
                    if (NMMA == 3) {
                        mma_tf32(acc[mt][nt], ahi[mt], blo[nt]);  // hi*lo
                        mma_tf32(acc[mt][nt], alo[mt], bhi[nt]);  // lo*hi
                    }
                }
        }

        asm volatile("cp.async.wait_group 0;\n");
        __syncthreads();
        st ^= 1;
    }

    // ---- epilogue ----
    #pragma unroll
    for (int mt = 0; mt < 4; mt++) {
        const int r0 = bm + wy * 64 + mt * 16 + lq;
        const int r1 = r0 + 8;
        #pragma unroll
        for (int nt = 0; nt < 4; nt++) {
            const int c = bn + wx * 32 + nt * 8 + lr * 2;
            const float2 bv = *(const float2*)(bias + c);
            if (HALF_OUT) {
                // store fp16 v transposed: [b][h][cell][HD], padded base
                const int h  = c >> 5;
                const int ch = c & 31;
                if (r0 < M) {
                    int b = r0 / LV, cell = r0 - b * LV;
                    size_t dst = VPAD + ((size_t)(b * NH + h) * LV + cell) * HD + ch;
                    *(__half2*)(Ch + dst) = __floats2half2_rn(acc[mt][nt][0] + bv.x,
                                                              acc[mt][nt][1] + bv.y);
                }
                if (r1 < M) {
                    int b = r1 / LV, cell = r1 - b * LV;
                    size_t dst = VPAD + ((size_t)(b * NH + h) * LV + cell) * HD + ch;
                    *(__half2*)(Ch + dst) = __floats2half2_rn(acc[mt][nt][2] + bv.x,
                                                              acc[mt][nt][3] + bv.y);
                }
            } else {
                if (r0 < M) {
                    float2 o0 = make_float2(acc[mt][nt][0] + bv.x, acc[mt][nt][1] + bv.y);
                    *(float2*)(C + (size_t)r0 * N + c) = o0;
                }
                if (r1 < M) {
                    float2 o1 = make_float2(acc[mt][nt][2] + bv.x, acc[mt][nt][3] + bv.y);
                    *(float2*)(C + (size_t)r1 * N + c) = o1;
                }
            }
        }
    }
}

// ---------------- fused softmax + location + bilinear sampling (fp16 v) -------
// One warp per (b, q, h). v layout [b][h][cell][HD] fp16: the two x-adjacent
// corners of a point are 128B contiguous -> one LDG.32 per row (lanes 0..15 =
// left cell as half2 channel pairs, lanes 16..31 = right cell). 2 loads/point.
__global__ __launch_bounds__(256, 8)
void msda_sample(const __half* __restrict__ vh,   // g_vh (padded)
                 const float* __restrict__ offr,  // [BS, LQ, EMBED]  (NH,SUMP,2)
                 const float* __restrict__ attnl, // [BS, LQ, NH*SUMP]
                 const float* __restrict__ refp,  // [BS, LQ, 4]
                 float* __restrict__ mid)         // [BS, LQ, EMBED]
{
    __shared__ int2   s_off[8][SUMP];   // half-element offsets of row0/row1 pair base
    __shared__ float4 s_w  [8][SUMP];   // {w00, w10, w01, w11} premultiplied

    const unsigned FULL = 0xffffffffu;
    const unsigned HALFM = 0x0000ffffu;  // lanes 0..15 only
    const int lane = threadIdx.x & 31;
    const int warp = threadIdx.x >> 5;
    const int wid  = (blockIdx.x * blockDim.x + threadIdx.x) >> 5;
    const int h = wid & (NH - 1);
    const int q = (wid >> 3) & (LQ - 1);
    const int b = wid >> 15;

    if (lane < SUMP) {
        const float4 ref = *(const float4*)(refp + ((size_t)b * LQ + q) * 4);
        const float* ob = offr + ((size_t)b * LQ + q) * EMBED + (h * SUMP + lane) * 2;
        const float offx = ob[0];
        const float offy = ob[1];
        const float logit = attnl[((size_t)b * LQ + q) * (NH * SUMP) + h * SUMP + lane];

        float m = logit;
        #pragma unroll
        for (int s = 8; s > 0; s >>= 1) m = fmaxf(m, __shfl_xor_sync(HALFM, m, s));
        float e = __expf(logit - m);
        float ssum = e;
        #pragma unroll
        for (int s = 8; s > 0; s >>= 1) ssum += __shfl_xor_sync(HALFM, ssum, s);
        const float pw = e / ssum;

        const float cx = ref.x + offx * 0.125f * ref.z;
        const float cy = ref.y + offy * 0.125f * ref.w;

        const int l  = lane >> 2;
        const int Wl = 80 >> l, Hl = 80 >> l;            // 80,40,20,10
        const int vs = (l == 0) ? 0 : (l == 1) ? 6400 : (l == 2) ? 8000 : 8400;

        const float x = cx * (float)Wl - 0.5f;
        const float y = cy * (float)Hl - 0.5f;
        const float x0f = floorf(x), y0f = floorf(y);
        const int x0 = (int)x0f, y0 = (int)y0f;
        const float lx = x - x0f, ly = y - y0f;

        const float vx0 = (x0 >= 0 && x0 < Wl)         ? 1.f : 0.f;
        const float vx1 = (x0 + 1 >= 0 && x0 + 1 < Wl) ? 1.f : 0.f;
        const float vy0 = (y0 >= 0 && y0 < Hl)         ? 1.f : 0.f;
        const float vy1 = (y0 + 1 >= 0 && y0 + 1 < Hl) ? 1.f : 0.f;

        // pair base x in [-1, Wl-1]; padding absorbs cells -1 and Hl*Wl
        const int xb  = min(max(x0, -1), Wl - 1);
        const int yc0 = min(max(y0, 0), Hl - 1);
        const int yc1 = min(max(y0 + 1, 0), Hl - 1);

        int2 off;
        off.x = (vs + yc0 * Wl + xb) * HD;   // half-element offset of left cell, row0
        off.y = (vs + yc1 * Wl + xb) * HD;   // row1

        float4 ww;
        ww.x = (1.f - lx) * (1.f - ly) * pw * (vx0 * vy0);  // left,  row0
        ww.y = lx * (1.f - ly) * pw * (vx1 * vy0);          // right, row0
        ww.z = (1.f - lx) * ly * pw * (vx0 * vy1);          // left,  row1
        ww.w = lx * ly * pw * (vx1 * vy1);                  // right, row1

        s_off[warp][lane] = off;
        s_w  [warp][lane] = ww;
    }
    __syncwarp();

    // lane covers 2 channels (2*(lane&15), +1) of left (lane<16) or right cell
    const __half* vb = vh + VPAD + (size_t)(b * NH + h) * LV * HD + 2 * lane;
    const bool left = (lane < 16);
    float accx = 0.f, accy = 0.f;

    #pragma unroll
    for (int p = 0; p < SUMP; p++) {
        const int2   off = s_off[warp][p];
        const float4 ww  = s_w  [warp][p];
        const float w0 = left ? ww.x : ww.y;
        const float w1 = left ? ww.z : ww.w;
        const float2 f0 = __half22float2(*(const __half2*)(vb + off.x));
        const float2 f1 = __half22float2(*(const __half2*)(vb + off.y));
        accx = fmaf(w0, f0.x, accx);
        accy = fmaf(w0, f0.y, accy);
        accx = fmaf(w1, f1.x, accx);
        accy = fmaf(w1, f1.y, accy);
    }

    // combine left/right partial sums: lanes i and i+16 hold same channel pair
    accx += __shfl_xor_sync(FULL, accx, 16);
    accy += __shfl_xor_sync(FULL, accy, 16);

    if (lane < 16) {
        float* dst = mid + ((size_t)b * LQ + q) * EMBED + h * HD + 2 * lane;
        *(float2*)dst = make_float2(accx, accy);
    }
}

// ---------------- launch ----------------
extern "C" void kernel_launch(void* const* d_in, const int* in_sizes, int n_in,
                              void* d_out, int out_size)
{
    const float* query  = (const float*)d_in[0];
    const float* refp   = (const float*)d_in[1];
    const float* value  = (const float*)d_in[2];
    const float* W_off  = (const float*)d_in[3];
    const float* b_off  = (const float*)d_in[4];
    const float* W_attn = (const float*)d_in[5];
    const float* b_attn = (const float*)d_in[6];
    const float* W_v    = (const float*)d_in[7];
    const float* b_v    = (const float*)d_in[8];
    const float* W_o    = (const float*)d_in[9];
    const float* b_o    = (const float*)d_in[10];
    float* out = (float*)d_out;

    __half* gvh;
    float *goff, *gattn, *gmid;
    cudaGetSymbolAddress((void**)&gvh,   g_vh);
    cudaGetSymbolAddress((void**)&goff,  g_off);
    cudaGetSymbolAddress((void**)&gattn, g_attn);
    cudaGetSymbolAddress((void**)&gmid,  g_mid);

    const int MV = BS * LV;   // 34000
    const int MQ = BS * LQ;   // 16384

    // 1) v = value @ W_v + b_v -> fp16 transposed [b][h][cell][HD]   (3x tf32)
    gemm_tf32_bias<true, 3><<<dim3(EMBED / BN, (MV + BM - 1) / BM), 256>>>(
        value, W_v, b_v, nullptr, gvh, MV, EMBED, EMBED);

    // 2) off = query @ W_off + b_off    [16384, 256]   (1x tf32; bias exact)
    gemm_tf32_bias<false, 1><<<dim3(EMBED / BN, MQ / BM), 256>>>(
        query, W_off, b_off, goff, nullptr, MQ, EMBED, EMBED);

    // 3) attn logits = query @ W_attn + b_attn   [16384, 128]   (1x tf32)
    gemm_tf32_bias<false, 1><<<dim3((NH * SUMP) / BN, MQ / BM), 256>>>(
        query, W_attn, b_attn, gattn, nullptr, MQ, NH * SUMP, EMBED);

    // 4) fused softmax + bilinear sampling -> g_mid [16384, 256]
    {
        const int total_warps = BS * LQ * NH;          // 131072
        const int threads = 256;                        // 8 warps/block
        const int blocks = total_warps / (threads / 32);
        msda_sample<<<blocks, threads>>>(gvh, goff, gattn, refp, gmid);
    }

    // 5) out = g_mid @ W_o + b_o        [16384, 256]   (3x tf32)
    gemm_tf32_bias<false, 3><<<dim3(EMBED / BN, MQ / BM), 256>>>(
        gmid, W_o, b_o, out, nullptr, MQ, EMBED, EMBED);
}

// round 13
// speedup vs baseline: 1.0019x; 1.0019x over previous
#include <cuda_runtime.h>
#include <cuda_bf16.h>
#include <cuda_fp16.h>
#include <cstdint>

// ---------------- problem constants ----------------
#define BS      4
#define LQ      4096
#define EMBED   256
#define NH      8
#define HD      32
#define LEVELS  4
#define NPTS    4
#define SUMP    16   // LEVELS*NPTS
#define LV      8500 // 80*80 + 40*40 + 20*20 + 10*10
#define VPAD    64   // halves of padding on each side of g_vh

// ---------------- scratch (static device globals; no allocation) ----------------
// v in fp16, layout [b][h][cell][HD], padded both ends for clamped-pair reads.
__device__ __half g_vh [(size_t)BS * NH * LV * HD + 2 * VPAD];
__device__ float g_off [(size_t)BS * LQ * EMBED];     // query @ W_off + b_off
__device__ float g_attn[(size_t)BS * LQ * NH * SUMP]; // query @ W_attn + b_attn
__device__ float g_mid [(size_t)BS * LQ * EMBED];     // sampled output before W_o

// ---------------- tf32 tensor-core GEMM: C = A[M,K] @ B[K,N] + bias[N] ----------
// 128x128 block tile, BK=16, 256 threads = 8 warps in 2x4 grid, warp tile 64x32.
// NMMA=3: error-compensated tf32 (Ootomo)  D += Ahi*Bhi + Ahi*Blo + Alo*Bhi.
// NMMA=1: plain tf32 (used where downstream sensitivity is low).
// 2-stage cp.async double buffering. HALF_OUT stores fp16 transposed v layout.
#define BM 128
#define BN 128
#define BK 16
#define A_STRIDE 20    // BK+4
#define B_STRIDE 136   // BN+8

__device__ __forceinline__ void mma_tf32(float* d, const uint32_t* a, const uint32_t* b)
{
    asm volatile(
        "mma.sync.aligned.m16n8k8.row.col.f32.tf32.tf32.f32 "
        "{%0,%1,%2,%3}, {%4,%5,%6,%7}, {%8,%9}, {%0,%1,%2,%3};\n"
        : "+f"(d[0]), "+f"(d[1]), "+f"(d[2]), "+f"(d[3])
        : "r"(a[0]), "r"(a[1]), "r"(a[2]), "r"(a[3]),
          "r"(b[0]), "r"(b[1]));
}

__device__ __forceinline__ uint32_t f2tf32(float x)
{
    uint32_t r;
    asm("cvt.rna.tf32.f32 %0, %1;" : "=r"(r) : "f"(x));
    return r;
}

__device__ __forceinline__ void cp_async16(void* smem_dst, const void* gsrc, int src_bytes)
{
    uint32_t s = (uint32_t)__cvta_generic_to_shared(smem_dst);
    asm volatile("cp.async.cg.shared.global [%0], [%1], 16, %2;\n"
                 :: "r"(s), "l"(gsrc), "r"(src_bytes));
}

template<bool HALF_OUT, int NMMA>
__global__ __launch_bounds__(256)
void gemm_tf32_bias(const float* __restrict__ A, const float* __restrict__ B,
                    const float* __restrict__ bias, float* __restrict__ C,
                    __half* __restrict__ Ch,
                    int M, int N, int K)
{
    __shared__ float As[2][BM][A_STRIDE];
    __shared__ float Bs[2][BK][B_STRIDE];

    const int tid  = threadIdx.x;
    const int lane = tid & 31;
    const int wrp  = tid >> 5;          // 0..7
    const int wy   = wrp >> 2;          // 0..1 : row group of 64
    const int wx   = wrp & 3;           // 0..3 : col group of 32
    const int bm   = blockIdx.y * BM;
    const int bn   = blockIdx.x * BN;

    const int lq = lane >> 2;           // 0..7
    const int lr = lane & 3;            // 0..3

    const int ar0 = tid >> 2;                 // 0..63
    const int ar1 = (tid + 256) >> 2;         // 64..127
    const int ac  = (tid & 3) << 2;           // 0,4,8,12
    const int br0 = tid >> 5;                 // 0..7
    const int br1 = (tid + 256) >> 5;         // 8..15
    const int bc  = (tid & 31) << 2;          // 0..124

    float acc[4][4][4] = {};            // [mt][nt][c0..c3]

    auto load_tiles = [&](int k0, int st) {
        {
            int row = ar0;
            int gr  = min(bm + row, M - 1);
            cp_async16(&As[st][row][ac], A + (size_t)gr * K + k0 + ac,
                       (bm + row < M) ? 16 : 0);
            row = ar1;
            gr  = min(bm + row, M - 1);
            cp_async16(&As[st][row][ac], A + (size_t)gr * K + k0 + ac,
                       (bm + row < M) ? 16 : 0);
        }
        cp_async16(&Bs[st][br0][bc], B + (size_t)(k0 + br0) * N + bn + bc, 16);
        cp_async16(&Bs[st][br1][bc], B + (size_t)(k0 + br1) * N + bn + bc, 16);
        asm volatile("cp.async.commit_group;\n");
    };

    load_tiles(0, 0);
    asm volatile("cp.async.wait_group 0;\n");
    __syncthreads();

    int st = 0;
    for (int k0 = 0; k0 < K; k0 += BK) {
        if (k0 + BK < K) load_tiles(k0 + BK, st ^ 1);

        #pragma unroll
        for (int k8 = 0; k8 < BK; k8 += 8) {
            uint32_t ahi[4][4], alo[4][4];
            #pragma unroll
            for (int mt = 0; mt < 4; mt++) {
                int r = wy * 64 + mt * 16 + lq;
                float a0 = As[st][r    ][k8 + lr    ];
                float a1 = As[st][r + 8][k8 + lr    ];
                float a2 = As[st][r    ][k8 + lr + 4];
                float a3 = As[st][r + 8][k8 + lr + 4];
                ahi[mt][0] = f2tf32(a0);
                ahi[mt][1] = f2tf32(a1);
                ahi[mt][2] = f2tf32(a2);
                ahi[mt][3] = f2tf32(a3);
                if (NMMA == 3) {
                    alo[mt][0] = __float_as_uint(a0 - __uint_as_float(ahi[mt][0]));
                    alo[mt][1] = __float_as_uint(a1 - __uint_as_float(ahi[mt][1]));
                    alo[mt][2] = __float_as_uint(a2 - __uint_as_float(ahi[mt][2]));
                    alo[mt][3] = __float_as_uint(a3 - __uint_as_float(ahi[mt][3]));
                }
            }
            uint32_t bhi[4][2], blo[4][2];
            #pragma unroll
            for (int nt = 0; nt < 4; nt++) {
                int c = wx * 32 + nt * 8 + lq;
                float b0 = Bs[st][k8 + lr    ][c];
                float b1 = Bs[st][k8 + lr + 4][c];
                bhi[nt][0] = f2tf32(b0);
                bhi[nt][1] = f2tf32(b1);
                if (NMMA == 3) {
                    blo[nt][0] = __float_as_uint(b0 - __uint_as_float(bhi[nt][0]));
                    blo[nt][1] = __float_as_uint(b1 - __uint_as_float(bhi[nt][1]));
                }
            }
            #pragma unroll
            for (int mt = 0; mt < 4; mt++)
                #pragma unroll
                for (int nt = 0; nt < 4; nt++) {
                    mma_tf32(acc[mt][nt], ahi[mt], bhi[nt]);      // hi*hi
                    if (NMMA == 3) {
                        mma_tf32(acc[mt][nt], ahi[mt], blo[nt]);  // hi*lo
                        mma_tf32(acc[mt][nt], alo[mt], bhi[nt]);  // lo*hi
                    }
                }
        }

        asm volatile("cp.async.wait_group 0;\n");
        __syncthreads();
        st ^= 1;
    }

    // ---- epilogue ----
    #pragma unroll
    for (int mt = 0; mt < 4; mt++) {
        const int r0 = bm + wy * 64 + mt * 16 + lq;
        const int r1 = r0 + 8;
        #pragma unroll
        for (int nt = 0; nt < 4; nt++) {
            const int c = bn + wx * 32 + nt * 8 + lr * 2;
            const float2 bv = *(const float2*)(bias + c);
            if (HALF_OUT) {
                // store fp16 v transposed: [b][h][cell][HD], padded base
                const int h  = c >> 5;
                const int ch = c & 31;
                if (r0 < M) {
                    int b = r0 / LV, cell = r0 - b * LV;
                    size_t dst = VPAD + ((size_t)(b * NH + h) * LV + cell) * HD + ch;
                    *(__half2*)(Ch + dst) = __floats2half2_rn(acc[mt][nt][0] + bv.x,
                                                              acc[mt][nt][1] + bv.y);
                }
                if (r1 < M) {
                    int b = r1 / LV, cell = r1 - b * LV;
                    size_t dst = VPAD + ((size_t)(b * NH + h) * LV + cell) * HD + ch;
                    *(__half2*)(Ch + dst) = __floats2half2_rn(acc[mt][nt][2] + bv.x,
                                                              acc[mt][nt][3] + bv.y);
                }
            } else {
                if (r0 < M) {
                    float2 o0 = make_float2(acc[mt][nt][0] + bv.x, acc[mt][nt][1] + bv.y);
                    *(float2*)(C + (size_t)r0 * N + c) = o0;
                }
                if (r1 < M) {
                    float2 o1 = make_float2(acc[mt][nt][2] + bv.x, acc[mt][nt][3] + bv.y);
                    *(float2*)(C + (size_t)r1 * N + c) = o1;
                }
            }
        }
    }
}

// ---------------- fused softmax + location + bilinear sampling (fp16 v) -------
// One warp per (b, q, h). v layout [b][h][cell][HD] fp16: the two x-adjacent
// corners of a point are 128B contiguous -> one LDG.32 per row (lanes 0..15 =
// left cell as half2 channel pairs, lanes 16..31 = right cell). 2 loads/point.
__global__ __launch_bounds__(256, 8)
void msda_sample(const __half* __restrict__ vh,   // g_vh (padded)
                 const float* __restrict__ offr,  // [BS, LQ, EMBED]  (NH,SUMP,2)
                 const float* __restrict__ attnl, // [BS, LQ, NH*SUMP]
                 const float* __restrict__ refp,  // [BS, LQ, 4]
                 float* __restrict__ mid)         // [BS, LQ, EMBED]
{
    __shared__ int2   s_off[8][SUMP];   // half-element offsets of row0/row1 pair base
    __shared__ float4 s_w  [8][SUMP];   // {w00, w10, w01, w11} premultiplied

    const unsigned FULL = 0xffffffffu;
    const unsigned HALFM = 0x0000ffffu;  // lanes 0..15 only
    const int lane = threadIdx.x & 31;
    const int warp = threadIdx.x >> 5;
    const int wid  = (blockIdx.x * blockDim.x + threadIdx.x) >> 5;
    const int h = wid & (NH - 1);
    const int q = (wid >> 3) & (LQ - 1);
    const int b = wid >> 15;

    if (lane < SUMP) {
        const float4 ref = *(const float4*)(refp + ((size_t)b * LQ + q) * 4);
        const float* ob = offr + ((size_t)b * LQ + q) * EMBED + (h * SUMP + lane) * 2;
        const float offx = ob[0];
        const float offy = ob[1];
        const float logit = attnl[((size_t)b * LQ + q) * (NH * SUMP) + h * SUMP + lane];

        float m = logit;
        #pragma unroll
        for (int s = 8; s > 0; s >>= 1) m = fmaxf(m, __shfl_xor_sync(HALFM, m, s));
        float e = __expf(logit - m);
        float ssum = e;
        #pragma unroll
        for (int s = 8; s > 0; s >>= 1) ssum += __shfl_xor_sync(HALFM, ssum, s);
        const float pw = e / ssum;

        const float cx = ref.x + offx * 0.125f * ref.z;
        const float cy = ref.y + offy * 0.125f * ref.w;

        const int l  = lane >> 2;
        const int Wl = 80 >> l, Hl = 80 >> l;            // 80,40,20,10
        const int vs = (l == 0) ? 0 : (l == 1) ? 6400 : (l == 2) ? 8000 : 8400;

        const float x = cx * (float)Wl - 0.5f;
        const float y = cy * (float)Hl - 0.5f;
        const float x0f = floorf(x), y0f = floorf(y);
        const int x0 = (int)x0f, y0 = (int)y0f;
        const float lx = x - x0f, ly = y - y0f;

        const float vx0 = (x0 >= 0 && x0 < Wl)         ? 1.f : 0.f;
        const float vx1 = (x0 + 1 >= 0 && x0 + 1 < Wl) ? 1.f : 0.f;
        const float vy0 = (y0 >= 0 && y0 < Hl)         ? 1.f : 0.f;
        const float vy1 = (y0 + 1 >= 0 && y0 + 1 < Hl) ? 1.f : 0.f;

        // pair base x in [-1, Wl-1]; padding absorbs cells -1 and Hl*Wl
        const int xb  = min(max(x0, -1), Wl - 1);
        const int yc0 = min(max(y0, 0), Hl - 1);
        const int yc1 = min(max(y0 + 1, 0), Hl - 1);

        int2 off;
        off.x = (vs + yc0 * Wl + xb) * HD;   // half-element offset of left cell, row0
        off.y = (vs + yc1 * Wl + xb) * HD;   // row1

        float4 ww;
        ww.x = (1.f - lx) * (1.f - ly) * pw * (vx0 * vy0);  // left,  row0
        ww.y = lx * (1.f - ly) * pw * (vx1 * vy0);          // right, row0
        ww.z = (1.f - lx) * ly * pw * (vx0 * vy1);          // left,  row1
        ww.w = lx * ly * pw * (vx1 * vy1);                  // right, row1

        s_off[warp][lane] = off;
        s_w  [warp][lane] = ww;
    }
    __syncwarp();

    // lane covers 2 channels (2*(lane&15), +1) of left (lane<16) or right cell
    const __half* vb = vh + VPAD + (size_t)(b * NH + h) * LV * HD + 2 * lane;
    const bool left = (lane < 16);
    float accx = 0.f, accy = 0.f;

    #pragma unroll
    for (int p = 0; p < SUMP; p++) {
        const int2   off = s_off[warp][p];
        const float4 ww  = s_w  [warp][p];
        const float w0 = left ? ww.x : ww.y;
        const float w1 = left ? ww.z : ww.w;
        const float2 f0 = __half22float2(*(const __half2*)(vb + off.x));
        const float2 f1 = __half22float2(*(const __half2*)(vb + off.y));
        accx = fmaf(w0, f0.x, accx);
        accy = fmaf(w0, f0.y, accy);
        accx = fmaf(w1, f1.x, accx);
        accy = fmaf(w1, f1.y, accy);
    }

    // combine left/right partial sums: lanes i and i+16 hold same channel pair
    accx += __shfl_xor_sync(FULL, accx, 16);
    accy += __shfl_xor_sync(FULL, accy, 16);

    if (lane < 16) {
        float* dst = mid + ((size_t)b * LQ + q) * EMBED + h * HD + 2 * lane;
        *(float2*)dst = make_float2(accx, accy);
    }
}

// ---------------- launch ----------------
extern "C" void kernel_launch(void* const* d_in, const int* in_sizes, int n_in,
                              void* d_out, int out_size)
{
    const float* query  = (const float*)d_in[0];
    const float* refp   = (const float*)d_in[1];
    const float* value  = (const float*)d_in[2];
    const float* W_off  = (const float*)d_in[3];
    const float* b_off  = (const float*)d_in[4];
    const float* W_attn = (const float*)d_in[5];
    const float* b_attn = (const float*)d_in[6];
    const float* W_v    = (const float*)d_in[7];
    const float* b_v    = (const float*)d_in[8];
    const float* W_o    = (const float*)d_in[9];
    const float* b_o    = (const float*)d_in[10];
    float* out = (float*)d_out;

    __half* gvh;
    float *goff, *gattn, *gmid;
    cudaGetSymbolAddress((void**)&gvh,   g_vh);
    cudaGetSymbolAddress((void**)&goff,  g_off);
    cudaGetSymbolAddress((void**)&gattn, g_attn);
    cudaGetSymbolAddress((void**)&gmid,  g_mid);

    const int MV = BS * LV;   // 34000
    const int MQ = BS * LQ;   // 16384

    // 1) v = value @ W_v + b_v -> fp16 transposed [b][h][cell][HD]   (3x tf32)
    gemm_tf32_bias<true, 3><<<dim3(EMBED / BN, (MV + BM - 1) / BM), 256>>>(
        value, W_v, b_v, nullptr, gvh, MV, EMBED, EMBED);

    // 2) off = query @ W_off + b_off    [16384, 256]   (1x tf32; bias exact)
    gemm_tf32_bias<false, 1><<<dim3(EMBED / BN, MQ / BM), 256>>>(
        query, W_off, b_off, goff, nullptr, MQ, EMBED, EMBED);

    // 3) attn logits = query @ W_attn + b_attn   [16384, 128]   (1x tf32)
    gemm_tf32_bias<false, 1><<<dim3((NH * SUMP) / BN, MQ / BM), 256>>>(
        query, W_attn, b_attn, gattn, nullptr, MQ, NH * SUMP, EMBED);

    // 4) fused softmax + bilinear sampling -> g_mid [16384, 256]
    {
        const int total_warps = BS * LQ * NH;          // 131072
        const int threads = 256;                        // 8 warps/block
        const int blocks = total_warps / (threads / 32);
        msda_sample<<<blocks, threads>>>(gvh, goff, gattn, refp, gmid);
    }

    // 5) out = g_mid @ W_o + b_o        [16384, 256]   (3x tf32)
    gemm_tf32_bias<false, 3><<<dim3(EMBED / BN, MQ / BM), 256>>>(
        gmid, W_o, b_o, out, nullptr, MQ, EMBED, EMBED);
}